// round 15
// baseline (speedup 1.0000x reference)
#include <cuda_runtime.h>
#include <math.h>

// Problem constants
#define BATCH 16
#define DEC   256
#define ENC   2048
#define DM    512
#define C2    1024   // 2*DM, encoder feature dim
#define C4    (C2/4) // 256 float4 per row

#define ECH   256           // 8-row chunks
#define EPER  (ENC/ECH)     // 8 rows per chunk

#define CTX4  (BATCH * DEC * C2 / 4)   // 1048576 float4
#define ATT4  (BATCH * DEC * ENC / 4)  // 2097152 float4

// Scratch (allocation-free rule: __device__ globals)
__device__ float  g_venc[C2];
__device__ float  g_score[BATCH * ENC];
__device__ float  g_prob[BATCH * ENC];
__device__ float  g_m[ECH][BATCH];
__device__ float  g_z[ECH][BATCH];
__device__ float4 g_ctx_part[ECH][BATCH][C4];  // 16 MB
__device__ float4 g_ctx[BATCH][C4];            // 64 KB

// ---------------------------------------------------------------------------
// Kernel 1: v_enc = W_enc . w_out, 4 threads per output (quad-split dot).
// 4096 threads = 16 blocks x 256. Quad q of thread handles c = gid>>2.
// ---------------------------------------------------------------------------
__global__ void venc_kernel(const float* __restrict__ W_enc,
                            const float* __restrict__ w_out) {
    int gid  = blockIdx.x * blockDim.x + threadIdx.x;   // 0..4095
    int c    = gid >> 2;
    int part = gid & 3;
    const float4* row = (const float4*)(W_enc + (size_t)c * DM);
    const float4* w4  = (const float4*)w_out;
    float acc = 0.f;
#pragma unroll
    for (int i = 0; i < 32; i++) {
        float4 a = __ldg(row + part + 4 * i);
        float4 b = __ldg(w4  + part + 4 * i);
        acc += a.x * b.x + a.y * b.y + a.z * b.z + a.w * b.w;
    }
    // sum within quad (full-warp shuffles; quads are lane-aligned)
    acc += __shfl_xor_sync(0xffffffffu, acc, 1);
    acc += __shfl_xor_sync(0xffffffffu, acc, 2);
    if (part == 0) g_venc[c] = acc;
}

// ---------------------------------------------------------------------------
// Kernel 2 (FUSED v2): block = (8-row chunk ch, batch b), 256 threads.
// Pass 1 (proven v5 stream): c16=t&63 col slice, rg=t>>6 -> rows 2rg,2rg+1.
//   Each float4 loaded is ALSO staged into smem sv[8][256] -> enc read from
//   DRAM exactly once by construction.
// Reduce: warp w -> row w (2 LDS + 5 shfl). Local softmax redundant per warp.
// Pass 2: ctx partial from sv (smem), weighted by sw.
// ---------------------------------------------------------------------------
__global__ void __launch_bounds__(256)
fused_kernel(const float4* __restrict__ enc4,
             const float* __restrict__ emask) {
    int ch = blockIdx.x;   // 0..255
    int b  = blockIdx.y;   // 0..15
    int t  = threadIdx.x;  // 0..255
    int lane = t & 31, wid = t >> 5;
    int rg  = t >> 6;      // 0..3
    int c16 = t & 63;      // 0..63

    __shared__ float4 sv[EPER][256];  // 32 KB staged chunk
    __shared__ float  ps[EPER][64];   // 2 KB partial dots
    __shared__ float  ss[EPER];       // masked scores
    __shared__ float  sw[EPER];       // local softmax weights

    const int rowbase = b * ENC + ch * EPER;

    float4 vv0 = __ldg(((const float4*)g_venc) + c16);
    float4 vv1 = __ldg(((const float4*)g_venc) + c16 + 64);
    float4 vv2 = __ldg(((const float4*)g_venc) + c16 + 128);
    float4 vv3 = __ldg(((const float4*)g_venc) + c16 + 192);

    // ---- Pass 1: stream rows 2rg, 2rg+1; stage + partial dot ----
#pragma unroll
    for (int k = 0; k < 2; k++) {
        int r = rg * 2 + k;
        const float4* rp = enc4 + (size_t)(rowbase + r) * C4 + c16;
        float4 a0 = __ldg(rp);
        float4 a1 = __ldg(rp + 64);
        float4 a2 = __ldg(rp + 128);
        float4 a3 = __ldg(rp + 192);
        sv[r][c16]       = a0;
        sv[r][c16 + 64]  = a1;
        sv[r][c16 + 128] = a2;
        sv[r][c16 + 192] = a3;
        float p0 = fmaf(a0.x, vv0.x, fmaf(a0.y, vv0.y, fmaf(a0.z, vv0.z, a0.w * vv0.w)));
        float p1 = fmaf(a1.x, vv1.x, fmaf(a1.y, vv1.y, fmaf(a1.z, vv1.z, a1.w * vv1.w)));
        float p2 = fmaf(a2.x, vv2.x, fmaf(a2.y, vv2.y, fmaf(a2.z, vv2.z, a2.w * vv2.w)));
        float p3 = fmaf(a3.x, vv3.x, fmaf(a3.y, vv3.y, fmaf(a3.z, vv3.z, a3.w * vv3.w)));
        ps[r][c16] = (p0 + p1) + (p2 + p3);
    }
    __syncthreads();

    // ---- Reduce: warp w owns row w (8 warps, 8 rows) ----
    {
        float s = ps[wid][lane] + ps[wid][lane + 32];
#pragma unroll
        for (int o = 16; o > 0; o >>= 1)
            s += __shfl_xor_sync(0xffffffffu, s, o);
        if (lane == 0) {
            int eg = rowbase + wid;
            s += logf(emask[eg]);
            g_score[eg] = s;
            ss[wid] = s;
        }
    }
    __syncthreads();

    // ---- Local softmax over 8 scores, redundant per warp (full-warp) ----
    {
        float s = (lane < EPER) ? ss[lane] : -1e30f;
        float m = s;
#pragma unroll
        for (int o = 16; o > 0; o >>= 1)
            m = fmaxf(m, __shfl_xor_sync(0xffffffffu, m, o));
        float w = (lane < EPER) ? expf(s - m) : 0.f;
        float z = w;
#pragma unroll
        for (int o = 16; o > 0; o >>= 1)
            z += __shfl_xor_sync(0xffffffffu, z, o);
        if (wid == 0) {
            if (lane < EPER) sw[lane] = w;
            if (lane == 0) { g_m[ch][b] = m; g_z[ch][b] = z; }
        }
    }
    __syncthreads();

    // ---- Pass 2: ctx partial from smem (enc NOT re-read) ----
    float4 acc = make_float4(0.f, 0.f, 0.f, 0.f);
#pragma unroll
    for (int e = 0; e < EPER; e++) {
        float4 v = sv[e][t];
        float w = sw[e];
        acc.x += w * v.x;
        acc.y += w * v.y;
        acc.z += w * v.z;
        acc.w += w * v.w;
    }
    g_ctx_part[ch][b][t] = acc;
}

// ---------------------------------------------------------------------------
// Kernel 3 (COMBINE): per batch b over 256 chunks.
//   M = max m_ch; Z = sum z_ch exp(m_ch-M); ctx = sum sc_ch*part; prob.
// All shuffles full-warp (R5-proven pattern).
// ---------------------------------------------------------------------------
__global__ void combine_kernel() {
    int b = blockIdx.x;
    int t = threadIdx.x;   // 0..255
    int lane = t & 31, wid = t >> 5;

    __shared__ float sc[ECH];    // exp(m_ch - M) / Z
    __shared__ float redm[8];
    __shared__ float redz[8];
    __shared__ float sMZ[2];

    float m_t = g_m[t][b];
    float z_t = g_z[t][b];

    float m = m_t;
#pragma unroll
    for (int o = 16; o > 0; o >>= 1)
        m = fmaxf(m, __shfl_xor_sync(0xffffffffu, m, o));
    if (lane == 0) redm[wid] = m;
    __syncthreads();

    if (wid == 0) {
        float v = (lane < 8) ? redm[lane] : -1e30f;
#pragma unroll
        for (int o = 16; o > 0; o >>= 1)
            v = fmaxf(v, __shfl_xor_sync(0xffffffffu, v, o));
        if (lane == 0) sMZ[0] = v;
    }
    __syncthreads();
    float M = sMZ[0];

    float zs = z_t * expf(m_t - M);
#pragma unroll
    for (int o = 16; o > 0; o >>= 1)
        zs += __shfl_xor_sync(0xffffffffu, zs, o);
    if (lane == 0) redz[wid] = zs;
    __syncthreads();

    if (wid == 0) {
        float v = (lane < 8) ? redz[lane] : 0.f;
#pragma unroll
        for (int o = 16; o > 0; o >>= 1)
            v += __shfl_xor_sync(0xffffffffu, v, o);
        if (lane == 0) sMZ[1] = v;
    }
    __syncthreads();
    float invZ = 1.f / sMZ[1];

    sc[t] = expf(m_t - M) * invZ;
    __syncthreads();

    float4 acc = make_float4(0.f, 0.f, 0.f, 0.f);
#pragma unroll 8
    for (int ch = 0; ch < ECH; ch++) {
        float4 v = g_ctx_part[ch][b][t];
        float s = sc[ch];
        acc.x += s * v.x;
        acc.y += s * v.y;
        acc.z += s * v.z;
        acc.w += s * v.w;
    }
    g_ctx[b][t] = acc;

#pragma unroll
    for (int i = 0; i < 8; i++) {
        int e = t + 256 * i;
        g_prob[b * ENC + e] = expf(g_score[b * ENC + e] - M) * invZ;
    }
}

// ---------------------------------------------------------------------------
// Kernel 4: WRITER, grid-stride x4 (both broadcast outputs).
// ---------------------------------------------------------------------------
__global__ void writer_kernel(float4* __restrict__ out_ctx,
                              float4* __restrict__ out_attn) {
    const int total  = CTX4 + ATT4;
    const int stride = gridDim.x * blockDim.x;
    for (int i4 = blockIdx.x * blockDim.x + threadIdx.x; i4 < total; i4 += stride) {
        if (i4 < CTX4) {
            int row = i4 >> 8;         // 256 float4 per row
            int c4  = i4 & 255;
            int b   = row >> 8;        // / DEC
            out_ctx[i4] = g_ctx[b][c4];
        } else {
            int j4 = i4 - CTX4;
            int row = j4 >> 9;         // 512 float4 per row
            int e4  = j4 & 511;
            int b   = row >> 8;        // / DEC
            out_attn[j4] = ((const float4*)g_prob)[b * 512 + e4];
        }
    }
}

// ---------------------------------------------------------------------------
// Launch (4 launches). Inputs: decoder_states, decoder_mask, encoder_states,
//   encoder_mask, W_enc, W_dec, w_out, b_out
// Output: [context (B*DEC*C2) | attn_dist (B*DEC*ENC)] floats
// ---------------------------------------------------------------------------
extern "C" void kernel_launch(void* const* d_in, const int* in_sizes, int n_in,
                              void* d_out, int out_size) {
    const float* enc   = (const float*)d_in[2];
    const float* emask = (const float*)d_in[3];
    const float* W_enc = (const float*)d_in[4];
    const float* w_out = (const float*)d_in[6];

    float* out_ctx  = (float*)d_out;
    float* out_attn = (float*)d_out + (size_t)BATCH * DEC * C2;

    venc_kernel<<<16, 256>>>(W_enc, w_out);

    dim3 gf(ECH, BATCH);
    fused_kernel<<<gf, 256>>>((const float4*)enc, emask);

    combine_kernel<<<BATCH, 256>>>();

    writer_kernel<<<(CTX4 + ATT4) / (4 * 256), 256>>>((float4*)out_ctx,
                                                      (float4*)out_attn);
}

// round 16
// speedup vs baseline: 1.3643x; 1.3643x over previous
#include <cuda_runtime.h>
#include <math.h>

// Problem constants
#define BATCH 16
#define DEC   256
#define ENC   2048
#define DM    512
#define C2    1024   // 2*DM, encoder feature dim
#define C4    (C2/4) // 256 float4 per row

#define ECH   256           // 8-row chunks
#define EPER  (ENC/ECH)     // 8 rows per chunk

#define CTX4  (BATCH * DEC * C2 / 4)   // 1048576 float4
#define ATT4  (BATCH * DEC * ENC / 4)  // 2097152 float4

// Scratch (allocation-free rule: __device__ globals)
__device__ float  g_venc[C2];
__device__ float  g_score[BATCH * ENC];
__device__ float  g_prob[BATCH * ENC];
__device__ float  g_m[ECH][BATCH];
__device__ float  g_z[ECH][BATCH];
__device__ float  g_sc[ECH][BATCH];            // exp(m_ch - M)/Z
__device__ float4 g_ctx_part[ECH][BATCH][C4];  // 16 MB
__device__ float4 g_ctx[BATCH][C4];            // 64 KB

// ---------------------------------------------------------------------------
// Kernel 1: v_enc = W_enc . w_out, 4 threads per output (16 blocks, fast).
// ---------------------------------------------------------------------------
__global__ void venc_kernel(const float* __restrict__ W_enc,
                            const float* __restrict__ w_out) {
    int gid  = blockIdx.x * blockDim.x + threadIdx.x;   // 0..4095
    int c    = gid >> 2;
    int part = gid & 3;
    const float4* row = (const float4*)(W_enc + (size_t)c * DM);
    const float4* w4  = (const float4*)w_out;
    float acc = 0.f;
#pragma unroll
    for (int i = 0; i < 32; i++) {
        float4 a = __ldg(row + part + 4 * i);
        float4 b = __ldg(w4  + part + 4 * i);
        acc += a.x * b.x + a.y * b.y + a.z * b.z + a.w * b.w;
    }
    acc += __shfl_xor_sync(0xffffffffu, acc, 1);
    acc += __shfl_xor_sync(0xffffffffu, acc, 2);
    if (part == 0) g_venc[c] = acc;
}

// Fillers so fused_kernel is the 4th launch (ncu capture window).
__global__ void fillerA_kernel() {}
__global__ void fillerB_kernel() {}

// ---------------------------------------------------------------------------
// Kernel 2 (FUSED v2, unchanged from R15 — passed): block = (8-row chunk,
// batch), 256 threads. Pass1 streams 8 rows (v5 pattern), staging each float4
// in smem sv -> enc read from DRAM exactly once. Reduce + local softmax +
// pass2 from smem.
// ---------------------------------------------------------------------------
__global__ void __launch_bounds__(256)
fused_kernel(const float4* __restrict__ enc4,
             const float* __restrict__ emask) {
    int ch = blockIdx.x;   // 0..255
    int b  = blockIdx.y;   // 0..15
    int t  = threadIdx.x;  // 0..255
    int lane = t & 31, wid = t >> 5;
    int rg  = t >> 6;      // 0..3
    int c16 = t & 63;      // 0..63

    __shared__ float4 sv[EPER][256];  // 32 KB staged chunk
    __shared__ float  ps[EPER][64];   // 2 KB partial dots
    __shared__ float  ss[EPER];       // masked scores
    __shared__ float  sw[EPER];       // local softmax weights

    const int rowbase = b * ENC + ch * EPER;

    float4 vv0 = __ldg(((const float4*)g_venc) + c16);
    float4 vv1 = __ldg(((const float4*)g_venc) + c16 + 64);
    float4 vv2 = __ldg(((const float4*)g_venc) + c16 + 128);
    float4 vv3 = __ldg(((const float4*)g_venc) + c16 + 192);

#pragma unroll
    for (int k = 0; k < 2; k++) {
        int r = rg * 2 + k;
        const float4* rp = enc4 + (size_t)(rowbase + r) * C4 + c16;
        float4 a0 = __ldg(rp);
        float4 a1 = __ldg(rp + 64);
        float4 a2 = __ldg(rp + 128);
        float4 a3 = __ldg(rp + 192);
        sv[r][c16]       = a0;
        sv[r][c16 + 64]  = a1;
        sv[r][c16 + 128] = a2;
        sv[r][c16 + 192] = a3;
        float p0 = fmaf(a0.x, vv0.x, fmaf(a0.y, vv0.y, fmaf(a0.z, vv0.z, a0.w * vv0.w)));
        float p1 = fmaf(a1.x, vv1.x, fmaf(a1.y, vv1.y, fmaf(a1.z, vv1.z, a1.w * vv1.w)));
        float p2 = fmaf(a2.x, vv2.x, fmaf(a2.y, vv2.y, fmaf(a2.z, vv2.z, a2.w * vv2.w)));
        float p3 = fmaf(a3.x, vv3.x, fmaf(a3.y, vv3.y, fmaf(a3.z, vv3.z, a3.w * vv3.w)));
        ps[r][c16] = (p0 + p1) + (p2 + p3);
    }
    __syncthreads();

    // Reduce: warp w owns row w
    {
        float s = ps[wid][lane] + ps[wid][lane + 32];
#pragma unroll
        for (int o = 16; o > 0; o >>= 1)
            s += __shfl_xor_sync(0xffffffffu, s, o);
        if (lane == 0) {
            int eg = rowbase + wid;
            s += logf(emask[eg]);
            g_score[eg] = s;
            ss[wid] = s;
        }
    }
    __syncthreads();

    // Local softmax over 8 scores, redundant per warp (full-warp shuffles)
    {
        float s = (lane < EPER) ? ss[lane] : -1e30f;
        float m = s;
#pragma unroll
        for (int o = 16; o > 0; o >>= 1)
            m = fmaxf(m, __shfl_xor_sync(0xffffffffu, m, o));
        float w = (lane < EPER) ? expf(s - m) : 0.f;
        float z = w;
#pragma unroll
        for (int o = 16; o > 0; o >>= 1)
            z += __shfl_xor_sync(0xffffffffu, z, o);
        if (wid == 0) {
            if (lane < EPER) sw[lane] = w;
            if (lane == 0) { g_m[ch][b] = m; g_z[ch][b] = z; }
        }
    }
    __syncthreads();

    // Pass 2: ctx partial from smem (enc NOT re-read)
    float4 acc = make_float4(0.f, 0.f, 0.f, 0.f);
#pragma unroll
    for (int e = 0; e < EPER; e++) {
        float4 v = sv[e][t];
        float w = sw[e];
        acc.x += w * v.x;
        acc.y += w * v.y;
        acc.z += w * v.z;
        acc.w += w * v.w;
    }
    g_ctx_part[ch][b][t] = acc;
}

// ---------------------------------------------------------------------------
// Kernel 3 (MZ): per batch. Warp 0: M = max_ch m, Z = sum z*exp(m-M) over the
// 256 chunks (8 per lane, static indexing, full-warp shuffles). Then all 256
// threads emit g_sc[ch][b] and probs (expf once per (b,e)).
// ---------------------------------------------------------------------------
__global__ void mz_kernel() {
    int b = blockIdx.x;
    int t = threadIdx.x;   // 0..255
    int lane = t & 31, wid = t >> 5;

    __shared__ float sMZ[2];

    if (wid == 0) {
        float mv0 = g_m[lane][b],       zv0 = g_z[lane][b];
        float mv1 = g_m[lane + 32][b],  zv1 = g_z[lane + 32][b];
        float mv2 = g_m[lane + 64][b],  zv2 = g_z[lane + 64][b];
        float mv3 = g_m[lane + 96][b],  zv3 = g_z[lane + 96][b];
        float mv4 = g_m[lane + 128][b], zv4 = g_z[lane + 128][b];
        float mv5 = g_m[lane + 160][b], zv5 = g_z[lane + 160][b];
        float mv6 = g_m[lane + 192][b], zv6 = g_z[lane + 192][b];
        float mv7 = g_m[lane + 224][b], zv7 = g_z[lane + 224][b];

        float m = fmaxf(fmaxf(fmaxf(mv0, mv1), fmaxf(mv2, mv3)),
                        fmaxf(fmaxf(mv4, mv5), fmaxf(mv6, mv7)));
#pragma unroll
        for (int o = 16; o > 0; o >>= 1)
            m = fmaxf(m, __shfl_xor_sync(0xffffffffu, m, o));

        float zs = zv0 * expf(mv0 - m) + zv1 * expf(mv1 - m)
                 + zv2 * expf(mv2 - m) + zv3 * expf(mv3 - m)
                 + zv4 * expf(mv4 - m) + zv5 * expf(mv5 - m)
                 + zv6 * expf(mv6 - m) + zv7 * expf(mv7 - m);
#pragma unroll
        for (int o = 16; o > 0; o >>= 1)
            zs += __shfl_xor_sync(0xffffffffu, zs, o);

        if (lane == 0) { sMZ[0] = m; sMZ[1] = 1.f / zs; }
    }
    __syncthreads();
    float M    = sMZ[0];
    float invZ = sMZ[1];

    g_sc[t][b] = expf(g_m[t][b] - M) * invZ;

#pragma unroll
    for (int i = 0; i < 8; i++) {
        int e = t + 256 * i;
        g_prob[b * ENC + e] = expf(g_score[b * ENC + e] - M) * invZ;
    }
}

// ---------------------------------------------------------------------------
// Kernel 4 (CTX REDUCE): grid (4 quarters, 16 b), 256 threads.
// Thread: col c4 = q*64 + (t&63), chunk group cg = t>>6 (64 chunks each).
// 64 coalesced loads/thread (MLP 8) + smem cross-group combine.
// ---------------------------------------------------------------------------
__global__ void ctx_reduce_kernel() {
    int q = blockIdx.x;    // 0..3
    int b = blockIdx.y;    // 0..15
    int t = threadIdx.x;   // 0..255
    int cg = t >> 6;       // 0..3
    int cc = t & 63;       // col within quarter
    int c4 = q * 64 + cc;

    float4 acc = make_float4(0.f, 0.f, 0.f, 0.f);
#pragma unroll 8
    for (int i = 0; i < 64; i++) {
        int ch = cg * 64 + i;
        float s  = g_sc[ch][b];
        float4 v = g_ctx_part[ch][b][c4];
        acc.x += s * v.x;
        acc.y += s * v.y;
        acc.z += s * v.z;
        acc.w += s * v.w;
    }

    __shared__ float4 red[4][64];
    red[cg][cc] = acc;
    __syncthreads();

    if (t < 64) {
        float4 a0 = red[0][t], a1 = red[1][t], a2 = red[2][t], a3 = red[3][t];
        float4 s;
        s.x = (a0.x + a1.x) + (a2.x + a3.x);
        s.y = (a0.y + a1.y) + (a2.y + a3.y);
        s.z = (a0.z + a1.z) + (a2.z + a3.z);
        s.w = (a0.w + a1.w) + (a2.w + a3.w);
        g_ctx[b][q * 64 + t] = s;
    }
}

// ---------------------------------------------------------------------------
// Kernel 5: WRITER, grid-stride x4 (both broadcast outputs).
// ---------------------------------------------------------------------------
__global__ void writer_kernel(float4* __restrict__ out_ctx,
                              float4* __restrict__ out_attn) {
    const int total  = CTX4 + ATT4;
    const int stride = gridDim.x * blockDim.x;
    for (int i4 = blockIdx.x * blockDim.x + threadIdx.x; i4 < total; i4 += stride) {
        if (i4 < CTX4) {
            int row = i4 >> 8;         // 256 float4 per row
            int c4  = i4 & 255;
            int b   = row >> 8;        // / DEC
            out_ctx[i4] = g_ctx[b][c4];
        } else {
            int j4 = i4 - CTX4;
            int row = j4 >> 9;         // 512 float4 per row
            int e4  = j4 & 511;
            int b   = row >> 8;        // / DEC
            out_attn[j4] = ((const float4*)g_prob)[b * 512 + e4];
        }
    }
}

// ---------------------------------------------------------------------------
// Launch. Inputs: decoder_states, decoder_mask, encoder_states, encoder_mask,
//   W_enc, W_dec, w_out, b_out
// Output: [context (B*DEC*C2) | attn_dist (B*DEC*ENC)] floats
// ---------------------------------------------------------------------------
extern "C" void kernel_launch(void* const* d_in, const int* in_sizes, int n_in,
                              void* d_out, int out_size) {
    const float* enc   = (const float*)d_in[2];
    const float* emask = (const float*)d_in[3];
    const float* W_enc = (const float*)d_in[4];
    const float* w_out = (const float*)d_in[6];

    float* out_ctx  = (float*)d_out;
    float* out_attn = (float*)d_out + (size_t)BATCH * DEC * C2;

    venc_kernel<<<16, 256>>>(W_enc, w_out);                // launch 1
    fillerA_kernel<<<1, 32>>>();                           // launch 2
    fillerB_kernel<<<1, 32>>>();                           // launch 3

    dim3 gf(ECH, BATCH);
    fused_kernel<<<gf, 256>>>((const float4*)enc, emask);  // launch 4 (profiled)

    mz_kernel<<<BATCH, 256>>>();                           // launch 5

    dim3 gr(4, BATCH);
    ctx_reduce_kernel<<<gr, 256>>>();                      // launch 6

    writer_kernel<<<(CTX4 + ATT4) / (4 * 256), 256>>>((float4*)out_ctx,
                                                      (float4*)out_attn);
}

// round 17
// speedup vs baseline: 1.4622x; 1.0717x over previous
#include <cuda_runtime.h>
#include <math.h>

// Problem constants
#define BATCH 16
#define DEC   256
#define ENC   2048
#define DM    512
#define C2    1024   // 2*DM, encoder feature dim
#define C4    (C2/4) // 256 float4 per row

#define ECH   256           // 8-row chunks
#define EPER  (ENC/ECH)     // 8 rows per chunk

#define CTX4  (BATCH * DEC * C2 / 4)   // 1048576 float4
#define ATT4  (BATCH * DEC * ENC / 4)  // 2097152 float4

// Scratch (allocation-free rule: __device__ globals)
__device__ float  g_venc[C2];
__device__ float  g_score[BATCH * ENC];
__device__ float  g_prob[BATCH * ENC];
__device__ float  g_m[ECH][BATCH];
__device__ float  g_z[ECH][BATCH];
__device__ float4 g_ctx_part[ECH][BATCH][C4];  // 16 MB
__device__ float4 g_ctx[BATCH][C4];            // 64 KB

// ---------------------------------------------------------------------------
// Kernel 1: v_enc = W_enc . w_out, 4 threads per output (16 blocks).
// ---------------------------------------------------------------------------
__global__ void venc_kernel(const float* __restrict__ W_enc,
                            const float* __restrict__ w_out) {
    int gid  = blockIdx.x * blockDim.x + threadIdx.x;   // 0..4095
    int c    = gid >> 2;
    int part = gid & 3;
    const float4* row = (const float4*)(W_enc + (size_t)c * DM);
    const float4* w4  = (const float4*)w_out;
    float acc = 0.f;
#pragma unroll
    for (int i = 0; i < 32; i++) {
        float4 a = __ldg(row + part + 4 * i);
        float4 b = __ldg(w4  + part + 4 * i);
        acc += a.x * b.x + a.y * b.y + a.z * b.z + a.w * b.w;
    }
    acc += __shfl_xor_sync(0xffffffffu, acc, 1);
    acc += __shfl_xor_sync(0xffffffffu, acc, 2);
    if (part == 0) g_venc[c] = acc;
}

// ---------------------------------------------------------------------------
// Kernel 2 (FUSED, PROVEN 32.1us @54% DRAM — unchanged): block = (8-row
// chunk, batch), 256 threads. Pass1 streams 8 rows (v5 pattern), staging
// each float4 in smem sv -> enc read from DRAM exactly once. Reduce + local
// softmax + pass2 from smem.
// ---------------------------------------------------------------------------
__global__ void __launch_bounds__(256)
fused_kernel(const float4* __restrict__ enc4,
             const float* __restrict__ emask) {
    int ch = blockIdx.x;   // 0..255
    int b  = blockIdx.y;   // 0..15
    int t  = threadIdx.x;  // 0..255
    int lane = t & 31, wid = t >> 5;
    int rg  = t >> 6;      // 0..3
    int c16 = t & 63;      // 0..63

    __shared__ float4 sv[EPER][256];  // 32 KB staged chunk
    __shared__ float  ps[EPER][64];   // 2 KB partial dots
    __shared__ float  ss[EPER];       // masked scores
    __shared__ float  sw[EPER];       // local softmax weights

    const int rowbase = b * ENC + ch * EPER;

    float4 vv0 = __ldg(((const float4*)g_venc) + c16);
    float4 vv1 = __ldg(((const float4*)g_venc) + c16 + 64);
    float4 vv2 = __ldg(((const float4*)g_venc) + c16 + 128);
    float4 vv3 = __ldg(((const float4*)g_venc) + c16 + 192);

#pragma unroll
    for (int k = 0; k < 2; k++) {
        int r = rg * 2 + k;
        const float4* rp = enc4 + (size_t)(rowbase + r) * C4 + c16;
        float4 a0 = __ldg(rp);
        float4 a1 = __ldg(rp + 64);
        float4 a2 = __ldg(rp + 128);
        float4 a3 = __ldg(rp + 192);
        sv[r][c16]       = a0;
        sv[r][c16 + 64]  = a1;
        sv[r][c16 + 128] = a2;
        sv[r][c16 + 192] = a3;
        float p0 = fmaf(a0.x, vv0.x, fmaf(a0.y, vv0.y, fmaf(a0.z, vv0.z, a0.w * vv0.w)));
        float p1 = fmaf(a1.x, vv1.x, fmaf(a1.y, vv1.y, fmaf(a1.z, vv1.z, a1.w * vv1.w)));
        float p2 = fmaf(a2.x, vv2.x, fmaf(a2.y, vv2.y, fmaf(a2.z, vv2.z, a2.w * vv2.w)));
        float p3 = fmaf(a3.x, vv3.x, fmaf(a3.y, vv3.y, fmaf(a3.z, vv3.z, a3.w * vv3.w)));
        ps[r][c16] = (p0 + p1) + (p2 + p3);
    }
    __syncthreads();

    // Reduce: warp w owns row w
    {
        float s = ps[wid][lane] + ps[wid][lane + 32];
#pragma unroll
        for (int o = 16; o > 0; o >>= 1)
            s += __shfl_xor_sync(0xffffffffu, s, o);
        if (lane == 0) {
            int eg = rowbase + wid;
            s += logf(emask[eg]);
            g_score[eg] = s;
            ss[wid] = s;
        }
    }
    __syncthreads();

    // Local softmax over 8 scores, redundant per warp (full-warp shuffles)
    {
        float s = (lane < EPER) ? ss[lane] : -1e30f;
        float m = s;
#pragma unroll
        for (int o = 16; o > 0; o >>= 1)
            m = fmaxf(m, __shfl_xor_sync(0xffffffffu, m, o));
        float w = (lane < EPER) ? expf(s - m) : 0.f;
        float z = w;
#pragma unroll
        for (int o = 16; o > 0; o >>= 1)
            z += __shfl_xor_sync(0xffffffffu, z, o);
        if (wid == 0) {
            if (lane < EPER) sw[lane] = w;
            if (lane == 0) { g_m[ch][b] = m; g_z[ch][b] = z; }
        }
    }
    __syncthreads();

    // Pass 2: ctx partial from smem (enc NOT re-read)
    float4 acc = make_float4(0.f, 0.f, 0.f, 0.f);
#pragma unroll
    for (int e = 0; e < EPER; e++) {
        float4 v = sv[e][t];
        float w = sw[e];
        acc.x += w * v.x;
        acc.y += w * v.y;
        acc.z += w * v.z;
        acc.w += w * v.w;
    }
    g_ctx_part[ch][b][t] = acc;
}

// ---------------------------------------------------------------------------
// Kernel 3 (REDUCE+MZ): grid (4 quarters, 16 b), 256 threads.
// Each block REDUNDANTLY computes M/Z (warp 0, 8 static reads/lane) — cheap,
// removes the separate mz launch. Then: sc[] in smem, ctx quarter via
// 64-chunk groups + smem combine, and this block's quarter of the probs.
// ---------------------------------------------------------------------------
__global__ void reduce_kernel() {
    int q = blockIdx.x;    // 0..3
    int b = blockIdx.y;    // 0..15
    int t = threadIdx.x;   // 0..255
    int lane = t & 31, wid = t >> 5;

    __shared__ float sMZ[2];
    __shared__ float ssc[ECH];
    __shared__ float4 red[4][64];

    if (wid == 0) {
        float mv0 = g_m[lane][b],       zv0 = g_z[lane][b];
        float mv1 = g_m[lane + 32][b],  zv1 = g_z[lane + 32][b];
        float mv2 = g_m[lane + 64][b],  zv2 = g_z[lane + 64][b];
        float mv3 = g_m[lane + 96][b],  zv3 = g_z[lane + 96][b];
        float mv4 = g_m[lane + 128][b], zv4 = g_z[lane + 128][b];
        float mv5 = g_m[lane + 160][b], zv5 = g_z[lane + 160][b];
        float mv6 = g_m[lane + 192][b], zv6 = g_z[lane + 192][b];
        float mv7 = g_m[lane + 224][b], zv7 = g_z[lane + 224][b];

        float m = fmaxf(fmaxf(fmaxf(mv0, mv1), fmaxf(mv2, mv3)),
                        fmaxf(fmaxf(mv4, mv5), fmaxf(mv6, mv7)));
#pragma unroll
        for (int o = 16; o > 0; o >>= 1)
            m = fmaxf(m, __shfl_xor_sync(0xffffffffu, m, o));

        float zs = zv0 * expf(mv0 - m) + zv1 * expf(mv1 - m)
                 + zv2 * expf(mv2 - m) + zv3 * expf(mv3 - m)
                 + zv4 * expf(mv4 - m) + zv5 * expf(mv5 - m)
                 + zv6 * expf(mv6 - m) + zv7 * expf(mv7 - m);
#pragma unroll
        for (int o = 16; o > 0; o >>= 1)
            zs += __shfl_xor_sync(0xffffffffu, zs, o);

        if (lane == 0) { sMZ[0] = m; sMZ[1] = 1.f / zs; }
    }
    __syncthreads();
    float M    = sMZ[0];
    float invZ = sMZ[1];

    ssc[t] = expf(g_m[t][b] - M) * invZ;
    __syncthreads();

    // ctx quarter: chunk group cg over 64 chunks, col c4 = q*64 + (t&63)
    int cg = t >> 6;
    int cc = t & 63;
    int c4 = q * 64 + cc;

    float4 acc = make_float4(0.f, 0.f, 0.f, 0.f);
#pragma unroll 8
    for (int i = 0; i < 64; i++) {
        int ch = cg * 64 + i;
        float s  = ssc[ch];
        float4 v = g_ctx_part[ch][b][c4];
        acc.x += s * v.x;
        acc.y += s * v.y;
        acc.z += s * v.z;
        acc.w += s * v.w;
    }
    red[cg][cc] = acc;
    __syncthreads();

    if (t < 64) {
        float4 a0 = red[0][t], a1 = red[1][t], a2 = red[2][t], a3 = red[3][t];
        float4 s;
        s.x = (a0.x + a1.x) + (a2.x + a3.x);
        s.y = (a0.y + a1.y) + (a2.y + a3.y);
        s.z = (a0.z + a1.z) + (a2.z + a3.z);
        s.w = (a0.w + a1.w) + (a2.w + a3.w);
        g_ctx[b][q * 64 + t] = s;
    }

    // probs quarter: e in [q*512, q*512+512), 2 per thread
    int e0 = q * 512 + t;
    g_prob[b * ENC + e0]       = expf(g_score[b * ENC + e0]       - M) * invZ;
    g_prob[b * ENC + e0 + 256] = expf(g_score[b * ENC + e0 + 256] - M) * invZ;
}

// ---------------------------------------------------------------------------
// Kernel 4: WRITER, grid-stride x4 (both broadcast outputs).
// ---------------------------------------------------------------------------
__global__ void writer_kernel(float4* __restrict__ out_ctx,
                              float4* __restrict__ out_attn) {
    const int total  = CTX4 + ATT4;
    const int stride = gridDim.x * blockDim.x;
    for (int i4 = blockIdx.x * blockDim.x + threadIdx.x; i4 < total; i4 += stride) {
        if (i4 < CTX4) {
            int row = i4 >> 8;         // 256 float4 per row
            int c4  = i4 & 255;
            int b   = row >> 8;        // / DEC
            out_ctx[i4] = g_ctx[b][c4];
        } else {
            int j4 = i4 - CTX4;
            int row = j4 >> 9;         // 512 float4 per row
            int e4  = j4 & 511;
            int b   = row >> 8;        // / DEC
            out_attn[j4] = ((const float4*)g_prob)[b * 512 + e4];
        }
    }
}

// ---------------------------------------------------------------------------
// Launch (4 launches). Inputs: decoder_states, decoder_mask, encoder_states,
//   encoder_mask, W_enc, W_dec, w_out, b_out
// Output: [context (B*DEC*C2) | attn_dist (B*DEC*ENC)] floats
// ---------------------------------------------------------------------------
extern "C" void kernel_launch(void* const* d_in, const int* in_sizes, int n_in,
                              void* d_out, int out_size) {
    const float* enc   = (const float*)d_in[2];
    const float* emask = (const float*)d_in[3];
    const float* W_enc = (const float*)d_in[4];
    const float* w_out = (const float*)d_in[6];

    float* out_ctx  = (float*)d_out;
    float* out_attn = (float*)d_out + (size_t)BATCH * DEC * C2;

    venc_kernel<<<16, 256>>>(W_enc, w_out);                // launch 1

    dim3 gf(ECH, BATCH);
    fused_kernel<<<gf, 256>>>((const float4*)enc, emask);  // launch 2

    dim3 gr(4, BATCH);
    reduce_kernel<<<gr, 256>>>();                          // launch 3

    writer_kernel<<<(CTX4 + ATT4) / (4 * 256), 256>>>((float4*)out_ctx,
                                                      (float4*)out_attn);  // launch 4 (profiled)
}